// round 9
// baseline (speedup 1.0000x reference)
#include <cuda_runtime.h>
#include <cuda_fp16.h>
#include <math.h>
#include <stdint.h>

#define BB 4
#define SS 1024
#define DD 1024
#define HH 16
#define HDIM 64
#define FF 4096
#define LL 6
#define MM (BB*SS)
#define EPSV 1e-5f

// ---------------- scratch (device globals; no allocation allowed) ----------------
__device__ float g_x[MM*DD];
__device__ float g_y[MM*DD];
__device__ __half g_a[MM*DD];
__device__ __half g_ffa[MM*FF];
__device__ __half g_q[BB*HH*SS*HDIM];
__device__ __half g_k[BB*HH*SS*HDIM];
__device__ __half g_v[BB*HH*SS*HDIM];
__device__ __half g_vo[MM*DD];
__device__ __half g_wqkv[(size_t)LL*3*DD*DD];
__device__ __half g_wout[(size_t)LL*DD*DD];
__device__ __half g_w1[(size_t)LL*DD*FF];
__device__ __half g_w2[(size_t)LL*FF*DD];

// ================= PTX building blocks =================
__device__ __forceinline__ uint32_t smem_u32(const void* p) {
    return (uint32_t)__cvta_generic_to_shared((void*)p);
}
__device__ __forceinline__ void ldsm_x4(uint32_t (&r)[4], uint32_t addr) {
    asm volatile("ldmatrix.sync.aligned.m8n8.x4.shared.b16 {%0,%1,%2,%3}, [%4];"
        : "=r"(r[0]), "=r"(r[1]), "=r"(r[2]), "=r"(r[3]) : "r"(addr));
}
__device__ __forceinline__ void ldsm_x4_t(uint32_t (&r)[4], uint32_t addr) {
    asm volatile("ldmatrix.sync.aligned.m8n8.x4.trans.shared.b16 {%0,%1,%2,%3}, [%4];"
        : "=r"(r[0]), "=r"(r[1]), "=r"(r[2]), "=r"(r[3]) : "r"(addr));
}
__device__ __forceinline__ void ldsm_x2(uint32_t (&r)[2], uint32_t addr) {
    asm volatile("ldmatrix.sync.aligned.m8n8.x2.shared.b16 {%0,%1}, [%2];"
        : "=r"(r[0]), "=r"(r[1]) : "r"(addr));
}
__device__ __forceinline__ void mma16816(float (&d)[4], const uint32_t (&a)[4],
                                         const uint32_t (&b)[2]) {
    asm volatile(
        "mma.sync.aligned.m16n8k16.row.col.f32.f16.f16.f32 "
        "{%0,%1,%2,%3}, {%4,%5,%6,%7}, {%8,%9}, {%0,%1,%2,%3};"
        : "+f"(d[0]), "+f"(d[1]), "+f"(d[2]), "+f"(d[3])
        : "r"(a[0]), "r"(a[1]), "r"(a[2]), "r"(a[3]), "r"(b[0]), "r"(b[1]));
}
__device__ __forceinline__ void mma16816b(float (&d)[4], const uint32_t (&a)[4],
                                          uint32_t b0, uint32_t b1) {
    asm volatile(
        "mma.sync.aligned.m16n8k16.row.col.f32.f16.f16.f32 "
        "{%0,%1,%2,%3}, {%4,%5,%6,%7}, {%8,%9}, {%0,%1,%2,%3};"
        : "+f"(d[0]), "+f"(d[1]), "+f"(d[2]), "+f"(d[3])
        : "r"(a[0]), "r"(a[1]), "r"(a[2]), "r"(a[3]), "r"(b0), "r"(b1));
}
__device__ __forceinline__ void cp16(uint32_t dst, const void* src) {
    asm volatile("cp.async.cg.shared.global [%0], [%1], 16;" :: "r"(dst), "l"(src));
}
#define CP_COMMIT() asm volatile("cp.async.commit_group;" ::: "memory")
#define CP_WAIT1()  asm volatile("cp.async.wait_group 1;" ::: "memory")
#define CP_WAIT0()  asm volatile("cp.async.wait_group 0;" ::: "memory")

__device__ __forceinline__ void store_h2(__half* p, size_t idx, float a, float b) {
    *(__half2*)(p + idx) = __floats2half2_rn(a, b);
}
__device__ __forceinline__ uint32_t pack2h(float a, float b) {
    __half2 h = __floats2half2_rn(a, b);
    return *(uint32_t*)&h;
}

// ================= tensor-core GEMM (fp16, 128x128 tile, 3-stage, occ 2) =========
#define GBM 128
#define GBN 128
#define GBK 32
#define ROWB 80
#define TILEB (128*ROWB)
#define STAGEB (2*TILEB)       // A + B: 20480
#define NSTG 3
#define GT_SMEM (NSTG*STAGEB)  // 61440 -> 2 CTAs/SM

template<int EPI>
__global__ __launch_bounds__(256, 2) void gemm_mma(
    const __half* __restrict__ A, const __half* __restrict__ B,
    const float* __restrict__ bias, float* __restrict__ Cf,
    __half* __restrict__ Ch, int N, int K)
{
    extern __shared__ char sm[];
    uint32_t sb = smem_u32(sm);
    int tid = threadIdx.x;
    int warp = tid >> 5, lane = tid & 31;
    int wm = warp >> 2, wn = warp & 3;     // 2 x 4 warp grid, warp tile 64x32
    int m0 = blockIdx.y * GBM, n0 = blockIdx.x * GBN;

    float acc[4][4][4];
    #pragma unroll
    for (int i = 0; i < 4; i++)
        #pragma unroll
        for (int j = 0; j < 4; j++)
            #pragma unroll
            for (int e = 0; e < 4; e++) acc[i][j][e] = 0.f;

    auto load_stage = [&](int s, int k0) {
        uint32_t base = sb + s * STAGEB;
        #pragma unroll
        for (int j = 0; j < 4; j++) {
            int ch = tid + 256 * j;
            int tile = ch >> 9, r = (ch >> 2) & 127, c = ch & 3;
            const __half* src = (tile == 0) ? A + (size_t)(m0 + r) * K + k0 + c * 8
                                            : B + (size_t)(n0 + r) * K + k0 + c * 8;
            cp16(base + tile * TILEB + r * ROWB + c * 16, src);
        }
    };

    int T = K / GBK;
    load_stage(0, 0);          CP_COMMIT();
    load_stage(1, GBK);        CP_COMMIT();

    int a_r = lane & 15, a_c8 = (lane >> 4) * 8;
    int b_r = lane & 7,  b_c8 = ((lane >> 3) & 1) * 8;

    for (int t = 0; t < T; t++) {
        if (t + 1 < T) { CP_WAIT1(); } else { CP_WAIT0(); }
        __syncthreads();
        if (t + 2 < T) { load_stage((t + 2) % NSTG, (t + 2) * GBK); CP_COMMIT(); }

        uint32_t base = sb + (t % NSTG) * STAGEB;
        #pragma unroll
        for (int kk = 0; kk < 2; kk++) {
            uint32_t af[4][4], bf[4][2];
            #pragma unroll
            for (int mi = 0; mi < 4; mi++) {
                int row = wm * 64 + mi * 16 + a_r;
                ldsm_x4(af[mi], base + row * ROWB + (kk * 16 + a_c8) * 2);
            }
            #pragma unroll
            for (int ni = 0; ni < 4; ni++) {
                int row = wn * 32 + ni * 8 + b_r;
                ldsm_x2(bf[ni], base + TILEB + row * ROWB + (kk * 16 + b_c8) * 2);
            }
            #pragma unroll
            for (int mi = 0; mi < 4; mi++)
                #pragma unroll
                for (int ni = 0; ni < 4; ni++)
                    mma16816(acc[mi][ni], af[mi], bf[ni]);
        }
    }

    int qr = lane >> 2, qc = (lane & 3) * 2;
    #pragma unroll
    for (int mi = 0; mi < 4; mi++) {
        #pragma unroll
        for (int ni = 0; ni < 4; ni++) {
            int gr = m0 + wm * 64 + mi * 16 + qr;
            int gc = n0 + wn * 32 + ni * 8 + qc;
            float b0 = bias[gc], b1 = bias[gc + 1];
            float v00 = acc[mi][ni][0] + b0, v01 = acc[mi][ni][1] + b1;
            float v10 = acc[mi][ni][2] + b0, v11 = acc[mi][ni][3] + b1;
            if (EPI == 0) {
                *(float2*)(Cf + (size_t)gr * N + gc)       = make_float2(v00, v01);
                *(float2*)(Cf + (size_t)(gr + 8) * N + gc) = make_float2(v10, v11);
            } else if (EPI == 1) {
                v00 = fmaxf(v00, 0.f); v01 = fmaxf(v01, 0.f);
                v10 = fmaxf(v10, 0.f); v11 = fmaxf(v11, 0.f);
                store_h2(Ch, (size_t)gr * N + gc,       v00, v01);
                store_h2(Ch, (size_t)(gr + 8) * N + gc, v10, v11);
            } else {
                int hh = gc / 192, inner = gc - hh * 192;
                int ty = inner >> 6, d = inner & 63;
                int bb = gr >> 10, si = gr & 1023;
                size_t dst = ((size_t)(bb * HH + hh) * SS + si) * HDIM + d;
                if (ty == 0) {
                    store_h2(g_q, dst,            v00 * 0.125f, v01 * 0.125f);
                    store_h2(g_q, dst + 8 * HDIM, v10 * 0.125f, v11 * 0.125f);
                } else if (ty == 1) {
                    store_h2(g_k, dst,            v00, v01);
                    store_h2(g_k, dst + 8 * HDIM, v10, v11);
                } else {
                    store_h2(g_v, dst,            v00, v01);
                    store_h2(g_v, dst + 8 * HDIM, v10, v11);
                }
            }
        }
    }
}

// ================= flash attention (fp16 single-term QK and PV) =================
#define FA_ROWF 144
#define FA_TILE (128*FA_ROWF)
#define FA_STAGE (2*FA_TILE)
#define FA_NSTG 3
#define FA_SMEM (FA_NSTG*FA_STAGE)

__global__ __launch_bounds__(256, 1) void flash_attn(const float* __restrict__ mask)
{
    extern __shared__ char sm[];
    uint32_t sb = smem_u32(sm);
    int tid = threadIdx.x, lane = tid & 31, w = tid >> 5;
    int qt = blockIdx.x, bh = blockIdx.y;
    int b = bh >> 4, h = bh & 15;
    size_t head = (size_t)bh * SS * HDIM;

    #pragma unroll
    for (int j = 0; j < 4; j++) {
        int ch = tid + 256 * j;
        int row = (ch >> 3) & 127, c = ch & 7;
        cp16(sb + row * FA_ROWF + c * 16,
             g_q + head + (size_t)(qt * 128 + row) * HDIM + c * 8);
    }
    CP_COMMIT(); CP_WAIT0();
    __syncthreads();

    uint32_t qf[4][4];
    {
        int ar = lane & 15, ac = (lane >> 4) * 8;
        #pragma unroll
        for (int kb = 0; kb < 4; kb++)
            ldsm_x4(qf[kb], sb + (w * 16 + ar) * FA_ROWF + (kb * 16 + ac) * 2);
    }
    __syncthreads();

    auto load_kv = [&](int s, int kt) {
        uint32_t base = sb + s * FA_STAGE;
        size_t goff = head + (size_t)(kt * 128) * HDIM;
        #pragma unroll
        for (int j = 0; j < 8; j++) {
            int ch = tid + 256 * j;
            int tile = ch >> 10, row = (ch >> 3) & 127, c = ch & 7;
            const __half* sp = (tile == 0) ? g_k : g_v;
            cp16(base + tile * FA_TILE + row * FA_ROWF + c * 16,
                 sp + goff + (size_t)row * HDIM + c * 8);
        }
    };
    load_kv(0, 0); CP_COMMIT();
    load_kv(1, 1); CP_COMMIT();

    int g = lane >> 2, t = lane & 3;
    int krow = (lane & 7) + ((lane >> 4) & 1) * 8, kcol = ((lane >> 3) & 1) * 8;
    int vrow = (lane & 7) + ((lane >> 3) & 1) * 8, vcol = ((lane >> 4) & 1) * 8;
    int qrow0 = qt * 128 + w * 16 + g;
    const float* mrow0 = mask + ((size_t)(b * SS + qrow0)) * SS;

    float m0v = -1e30f, m1v = -1e30f, l0v = 0.f, l1v = 0.f;
    float o[8][4];
    #pragma unroll
    for (int nf = 0; nf < 8; nf++)
        #pragma unroll
        for (int e = 0; e < 4; e++) o[nf][e] = 0.f;

    const int T = 8;
    for (int kt = 0; kt < T; kt++) {
        if (kt < T - 1) { CP_WAIT1(); } else { CP_WAIT0(); }
        __syncthreads();
        if (kt + 2 < T) { load_kv((kt + 2) % FA_NSTG, kt + 2); CP_COMMIT(); }
        uint32_t base = sb + (kt % FA_NSTG) * FA_STAGE;

        float s[16][4];
        #pragma unroll
        for (int np = 0; np < 8; np++) {
            #pragma unroll
            for (int e = 0; e < 4; e++) { s[2*np][e] = 0.f; s[2*np+1][e] = 0.f; }
            #pragma unroll
            for (int kb = 0; kb < 4; kb++) {
                uint32_t ka = base + (np * 16 + krow) * FA_ROWF + (kb * 16 + kcol) * 2;
                uint32_t k4[4];
                ldsm_x4(k4, ka);
                mma16816b(s[2*np],   qf[kb], k4[0], k4[1]);
                mma16816b(s[2*np+1], qf[kb], k4[2], k4[3]);
            }
        }

        float mx0 = -1e30f, mx1 = -1e30f;
        #pragma unroll
        for (int ni = 0; ni < 16; ni++) {
            const float* mp = mrow0 + kt * 128 + ni * 8 + 2 * t;
            float2 mk0 = *(const float2*)mp;
            float2 mk1 = *(const float2*)(mp + 8 * SS);
            s[ni][0] += mk0.x; s[ni][1] += mk0.y;
            s[ni][2] += mk1.x; s[ni][3] += mk1.y;
            mx0 = fmaxf(mx0, fmaxf(s[ni][0], s[ni][1]));
            mx1 = fmaxf(mx1, fmaxf(s[ni][2], s[ni][3]));
        }
        mx0 = fmaxf(mx0, __shfl_xor_sync(0xffffffffu, mx0, 1));
        mx0 = fmaxf(mx0, __shfl_xor_sync(0xffffffffu, mx0, 2));
        mx1 = fmaxf(mx1, __shfl_xor_sync(0xffffffffu, mx1, 1));
        mx1 = fmaxf(mx1, __shfl_xor_sync(0xffffffffu, mx1, 2));
        float mn0 = fmaxf(m0v, mx0), mn1 = fmaxf(m1v, mx1);
        float a0 = __expf(m0v - mn0), a1 = __expf(m1v - mn1);
        m0v = mn0; m1v = mn1;
        l0v *= a0; l1v *= a1;
        #pragma unroll
        for (int nf = 0; nf < 8; nf++) {
            o[nf][0] *= a0; o[nf][1] *= a0; o[nf][2] *= a1; o[nf][3] *= a1;
        }
        #pragma unroll
        for (int ni = 0; ni < 16; ni++) {
            s[ni][0] = __expf(s[ni][0] - mn0); s[ni][1] = __expf(s[ni][1] - mn0);
            s[ni][2] = __expf(s[ni][2] - mn1); s[ni][3] = __expf(s[ni][3] - mn1);
            l0v += s[ni][0] + s[ni][1];
            l1v += s[ni][2] + s[ni][3];
        }

        #pragma unroll
        for (int ks = 0; ks < 8; ks++) {
            uint32_t pa[4];
            pa[0] = pack2h(s[2*ks][0],   s[2*ks][1]);
            pa[1] = pack2h(s[2*ks][2],   s[2*ks][3]);
            pa[2] = pack2h(s[2*ks+1][0], s[2*ks+1][1]);
            pa[3] = pack2h(s[2*ks+1][2], s[2*ks+1][3]);
            #pragma unroll
            for (int nv = 0; nv < 4; nv++) {
                uint32_t va = base + FA_TILE + (ks * 16 + vrow) * FA_ROWF
                              + (nv * 16 + vcol) * 2;
                uint32_t v4[4];
                ldsm_x4_t(v4, va);
                mma16816b(o[2*nv],   pa, v4[0], v4[1]);
                mma16816b(o[2*nv+1], pa, v4[2], v4[3]);
            }
        }
    }

    l0v += __shfl_xor_sync(0xffffffffu, l0v, 1);
    l0v += __shfl_xor_sync(0xffffffffu, l0v, 2);
    l1v += __shfl_xor_sync(0xffffffffu, l1v, 1);
    l1v += __shfl_xor_sync(0xffffffffu, l1v, 2);
    float inv0 = 1.f / l0v, inv1 = 1.f / l1v;
    size_t orow0 = (size_t)(b * SS + qrow0) * DD + h * HDIM;
    size_t orow1 = orow0 + (size_t)8 * DD;
    #pragma unroll
    for (int nf = 0; nf < 8; nf++) {
        int col = nf * 8 + 2 * t;
        store_h2(g_vo, orow0 + col, o[nf][0] * inv0, o[nf][1] * inv0);
        store_h2(g_vo, orow1 + col, o[nf][2] * inv1, o[nf][3] * inv1);
    }
}

// ================= weight transpose (fp16 single) =================
__global__ __launch_bounds__(256) void wsplit_t(const float* __restrict__ W,
                                                __half* __restrict__ hi,
                                                int Kdim, int Ndim) {
    __shared__ float t[32][33];
    size_t loff = (size_t)blockIdx.z * Kdim * Ndim;
    const float* Wl = W + loff;
    __half* hil = hi + loff;
    int k0 = blockIdx.y * 32, n0 = blockIdx.x * 32;
    int tx = threadIdx.x, ty = threadIdx.y;
    #pragma unroll
    for (int i = 0; i < 32; i += 8)
        t[ty + i][tx] = Wl[(size_t)(k0 + ty + i) * Ndim + n0 + tx];
    __syncthreads();
    #pragma unroll
    for (int i = 0; i < 32; i += 8) {
        int n = n0 + ty + i, k = k0 + tx;
        hil[(size_t)n * Kdim + k] = __float2half_rn(t[tx][ty + i]);
    }
}

// ================= embed + PE =================
__global__ __launch_bounds__(256) void embed_kernel(const int* __restrict__ tokens,
                                                    const float* __restrict__ emb,
                                                    float* __restrict__ x,
                                                    __half* __restrict__ xh) {
    int row = blockIdx.x;
    int s = row & (SS - 1);
    int tok = tokens[row];
    const float* e = emb + (size_t)tok * DD;
    int d0 = threadIdx.x * 4;
    float v[4];
    #pragma unroll
    for (int j = 0; j < 4; j++) {
        int d = d0 + j;
        int i2 = d & ~1;
        float denom = powf(10000.0f, (float)i2 / (float)DD);
        float ang = (float)s / denom;
        float pe = (d & 1) ? cosf(ang) : sinf(ang);
        v[j] = e[d] + pe;
    }
    size_t base = (size_t)row * DD + d0;
    *(float4*)(x + base) = make_float4(v[0], v[1], v[2], v[3]);
    store_h2(xh, base, v[0], v[1]);
    store_h2(xh, base + 2, v[2], v[3]);
}

// ================= residual + LayerNorm =================
__device__ __forceinline__ float warpReduceSum(float v) {
    #pragma unroll
    for (int o = 16; o; o >>= 1) v += __shfl_xor_sync(0xffffffffu, v, o);
    return v;
}
__device__ __forceinline__ float blockReduceSum(float v, float* sh) {
    v = warpReduceSum(v);
    int w = threadIdx.x >> 5;
    __syncthreads();
    if ((threadIdx.x & 31) == 0) sh[w] = v;
    __syncthreads();
    if (threadIdx.x < 32) {
        float t = (threadIdx.x < 8) ? sh[threadIdx.x] : 0.f;
        t = warpReduceSum(t);
        if (threadIdx.x == 0) sh[0] = t;
    }
    __syncthreads();
    return sh[0];
}

__global__ __launch_bounds__(256) void ln_kernel(const float* __restrict__ x,
                                                 const float* __restrict__ y,
                                                 const float* __restrict__ gamma,
                                                 const float* __restrict__ beta,
                                                 float* __restrict__ out,
                                                 __half* __restrict__ oh) {
    __shared__ float sh[8];
    size_t row = blockIdx.x;
    int d0 = threadIdx.x * 4;
    float4 a = *(const float4*)(x + row * DD + d0);
    float4 b4 = *(const float4*)(y + row * DD + d0);
    float z[4] = { a.x + b4.x, a.y + b4.y, a.z + b4.z, a.w + b4.w };
    float ssum = z[0] + z[1] + z[2] + z[3];
    ssum = blockReduceSum(ssum, sh);
    float mean = ssum * (1.0f / DD);
    float d2 = 0.f;
    #pragma unroll
    for (int e = 0; e < 4; e++) { float u = z[e] - mean; d2 += u * u; }
    d2 = blockReduceSum(d2, sh);
    float inv = rsqrtf(d2 * (1.0f / DD) + EPSV);
    float4 g4 = *(const float4*)(gamma + d0);
    float4 be4 = *(const float4*)(beta + d0);
    float o0 = g4.x * ((z[0] - mean) * inv) + be4.x;
    float o1 = g4.y * ((z[1] - mean) * inv) + be4.y;
    float o2 = g4.z * ((z[2] - mean) * inv) + be4.z;
    float o3 = g4.w * ((z[3] - mean) * inv) + be4.w;
    size_t base = row * DD + d0;
    *(float4*)(out + base) = make_float4(o0, o1, o2, o3);
    store_h2(oh, base, o0, o1);
    store_h2(oh, base + 2, o2, o3);
}

// ================= orchestration =================
extern "C" void kernel_launch(void* const* d_in, const int* in_sizes, int n_in,
                              void* d_out, int out_size) {
    const int*   tokens = (const int*)d_in[0];
    const float* mask   = (const float*)d_in[1];
    const float* emb    = (const float*)d_in[2];
    const float* qkv_w  = (const float*)d_in[3];
    const float* qkv_b  = (const float*)d_in[4];
    const float* out_w  = (const float*)d_in[5];
    const float* out_b  = (const float*)d_in[6];
    const float* w1     = (const float*)d_in[7];
    const float* b1     = (const float*)d_in[8];
    const float* w2     = (const float*)d_in[9];
    const float* b2     = (const float*)d_in[10];
    const float* gamma  = (const float*)d_in[11];
    const float* beta   = (const float*)d_in[12];
    float* out = (float*)d_out;

    float *px, *py;
    cudaGetSymbolAddress((void**)&px, g_x);
    cudaGetSymbolAddress((void**)&py, g_y);
    __half *pa, *pffa, *pvo, *pwq, *pwo, *pw1, *pw2;
    cudaGetSymbolAddress((void**)&pa,   g_a);
    cudaGetSymbolAddress((void**)&pffa, g_ffa);
    cudaGetSymbolAddress((void**)&pvo,  g_vo);
    cudaGetSymbolAddress((void**)&pwq,  g_wqkv);
    cudaGetSymbolAddress((void**)&pwo,  g_wout);
    cudaGetSymbolAddress((void**)&pw1,  g_w1);
    cudaGetSymbolAddress((void**)&pw2,  g_w2);

    cudaFuncSetAttribute(gemm_mma<0>, cudaFuncAttributeMaxDynamicSharedMemorySize, GT_SMEM);
    cudaFuncSetAttribute(gemm_mma<1>, cudaFuncAttributeMaxDynamicSharedMemorySize, GT_SMEM);
    cudaFuncSetAttribute(gemm_mma<2>, cudaFuncAttributeMaxDynamicSharedMemorySize, GT_SMEM);
    cudaFuncSetAttribute(flash_attn, cudaFuncAttributeMaxDynamicSharedMemorySize, FA_SMEM);

    wsplit_t<<<dim3(3 * DD / 32, DD / 32, LL), dim3(32, 8)>>>(qkv_w, pwq, DD, 3 * DD);
    wsplit_t<<<dim3(DD / 32, DD / 32, LL),     dim3(32, 8)>>>(out_w, pwo, DD, DD);
    wsplit_t<<<dim3(FF / 32, DD / 32, LL),     dim3(32, 8)>>>(w1, pw1, DD, FF);
    wsplit_t<<<dim3(DD / 32, FF / 32, LL),     dim3(32, 8)>>>(w2, pw2, FF, DD);

    embed_kernel<<<MM, 256>>>(tokens, emb, px, pa);

    for (int i = 0; i < LL; i++) {
        size_t l = (size_t)i;
        gemm_mma<2><<<dim3(3 * DD / GBN, MM / GBM), 256, GT_SMEM>>>(
            pa, pwq + l * 3 * DD * DD, qkv_b + l * 3 * DD, nullptr, nullptr, 3 * DD, DD);
        flash_attn<<<dim3(SS / 128, BB * HH), 256, FA_SMEM>>>(mask);
        gemm_mma<0><<<dim3(DD / GBN, MM / GBM), 256, GT_SMEM>>>(
            pvo, pwo + l * DD * DD, out_b + l * DD, py, nullptr, DD, DD);
        ln_kernel<<<MM, 256>>>(px, py, gamma + l * DD, beta + l * DD, px, pa);
        gemm_mma<1><<<dim3(FF / GBN, MM / GBM), 256, GT_SMEM>>>(
            pa, pw1 + l * DD * FF, b1 + l * FF, nullptr, pffa, FF, DD);
        gemm_mma<0><<<dim3(DD / GBN, MM / GBM), 256, GT_SMEM>>>(
            pffa, pw2 + l * FF * DD, b2 + l * DD, py, nullptr, DD, FF);
        ln_kernel<<<MM, 256>>>(px, py, gamma + l * DD, beta + l * DD,
                               (i == LL - 1) ? out : px, pa);
    }
}

// round 10
// speedup vs baseline: 1.3904x; 1.3904x over previous
#include <cuda_runtime.h>
#include <cuda_fp16.h>
#include <math.h>
#include <stdint.h>

#define BB 4
#define SS 1024
#define DD 1024
#define HH 16
#define HDIM 64
#define FF 4096
#define LL 6
#define MM (BB*SS)
#define EPSV 1e-5f

// ---------------- scratch (device globals; no allocation allowed) ----------------
__device__ float g_x[MM*DD];
__device__ float g_y[MM*DD];
__device__ __half g_a[MM*DD];
__device__ __half g_ffa[MM*FF];
__device__ __half g_q[BB*HH*SS*HDIM];
__device__ __half g_k[BB*HH*SS*HDIM];
__device__ __half g_v[BB*HH*SS*HDIM];
__device__ __half g_vo[MM*DD];
__device__ __half g_wqkv[(size_t)LL*3*DD*DD];
__device__ __half g_wout[(size_t)LL*DD*DD];
__device__ __half g_w1[(size_t)LL*DD*FF];
__device__ __half g_w2[(size_t)LL*FF*DD];

// ================= PTX building blocks =================
__device__ __forceinline__ uint32_t smem_u32(const void* p) {
    return (uint32_t)__cvta_generic_to_shared((void*)p);
}
__device__ __forceinline__ void ldsm_x4(uint32_t (&r)[4], uint32_t addr) {
    asm volatile("ldmatrix.sync.aligned.m8n8.x4.shared.b16 {%0,%1,%2,%3}, [%4];"
        : "=r"(r[0]), "=r"(r[1]), "=r"(r[2]), "=r"(r[3]) : "r"(addr));
}
__device__ __forceinline__ void ldsm_x4_t(uint32_t (&r)[4], uint32_t addr) {
    asm volatile("ldmatrix.sync.aligned.m8n8.x4.trans.shared.b16 {%0,%1,%2,%3}, [%4];"
        : "=r"(r[0]), "=r"(r[1]), "=r"(r[2]), "=r"(r[3]) : "r"(addr));
}
__device__ __forceinline__ void mma16816b(float (&d)[4], const uint32_t (&a)[4],
                                          uint32_t b0, uint32_t b1) {
    asm volatile(
        "mma.sync.aligned.m16n8k16.row.col.f32.f16.f16.f32 "
        "{%0,%1,%2,%3}, {%4,%5,%6,%7}, {%8,%9}, {%0,%1,%2,%3};"
        : "+f"(d[0]), "+f"(d[1]), "+f"(d[2]), "+f"(d[3])
        : "r"(a[0]), "r"(a[1]), "r"(a[2]), "r"(a[3]), "r"(b0), "r"(b1));
}
__device__ __forceinline__ void cp16(uint32_t dst, const void* src) {
    asm volatile("cp.async.cg.shared.global [%0], [%1], 16;" :: "r"(dst), "l"(src));
}
#define CP_COMMIT() asm volatile("cp.async.commit_group;" ::: "memory")
#define CP_WAIT2()  asm volatile("cp.async.wait_group 2;" ::: "memory")
#define CP_WAIT1()  asm volatile("cp.async.wait_group 1;" ::: "memory")
#define CP_WAIT0()  asm volatile("cp.async.wait_group 0;" ::: "memory")

__device__ __forceinline__ void store_h2(__half* p, size_t idx, float a, float b) {
    *(__half2*)(p + idx) = __floats2half2_rn(a, b);
}
__device__ __forceinline__ uint32_t pack2h(float a, float b) {
    __half2 h = __floats2half2_rn(a, b);
    return *(uint32_t*)&h;
}

// ================= tensor-core GEMM (fp16, 256x128 CTA tile, 4-stage) ============
// (R8 configuration — best measured GEMM)
#define GBM 256
#define GBN 128
#define GBK 32
#define ROWB 80
#define ATILE (256*ROWB)
#define BTILE (128*ROWB)
#define STAGEB (ATILE+BTILE)
#define NSTG 4
#define GT_SMEM (NSTG*STAGEB)

template<int EPI>
__global__ __launch_bounds__(256, 1) void gemm_mma(
    const __half* __restrict__ A, const __half* __restrict__ B,
    const float* __restrict__ bias, float* __restrict__ Cf,
    __half* __restrict__ Ch, int N, int K)
{
    extern __shared__ char sm[];
    uint32_t sb = smem_u32(sm);
    int tid = threadIdx.x;
    int warp = tid >> 5, lane = tid & 31;
    int wm = warp >> 1, wn = warp & 1;
    int m0 = blockIdx.y * GBM, n0 = blockIdx.x * GBN;

    float acc[4][8][4];
    #pragma unroll
    for (int i = 0; i < 4; i++)
        #pragma unroll
        for (int j = 0; j < 8; j++)
            #pragma unroll
            for (int e = 0; e < 4; e++) acc[i][j][e] = 0.f;

    auto load_stage = [&](int s, int k0) {
        uint32_t base = sb + s * STAGEB;
        #pragma unroll
        for (int j = 0; j < 6; j++) {
            int ch = tid + 256 * j;
            if (ch < 1024) {
                int r = ch >> 2, c = ch & 3;
                cp16(base + r * ROWB + c * 16, A + (size_t)(m0 + r) * K + k0 + c * 8);
            } else {
                int idx = ch - 1024;
                int r = idx >> 2, c = idx & 3;
                cp16(base + ATILE + r * ROWB + c * 16,
                     B + (size_t)(n0 + r) * K + k0 + c * 8);
            }
        }
    };

    int T = K / GBK;
    load_stage(0, 0);          CP_COMMIT();
    load_stage(1, GBK);        CP_COMMIT();
    load_stage(2, 2 * GBK);    CP_COMMIT();

    int a_r = lane & 15, a_c8 = (lane >> 4) * 8;

    for (int t = 0; t < T; t++) {
        if (t + 2 < T)      { CP_WAIT2(); }
        else if (t + 1 < T) { CP_WAIT1(); }
        else                { CP_WAIT0(); }
        __syncthreads();
        if (t + 3 < T) { load_stage((t + 3) & (NSTG - 1), (t + 3) * GBK); CP_COMMIT(); }

        uint32_t base = sb + (t & (NSTG - 1)) * STAGEB;
        #pragma unroll
        for (int kk = 0; kk < 2; kk++) {
            uint32_t af[4][4], bq[4][4];
            #pragma unroll
            for (int mi = 0; mi < 4; mi++) {
                int row = wm * 64 + mi * 16 + a_r;
                ldsm_x4(af[mi], base + row * ROWB + (kk * 16 + a_c8) * 2);
            }
            #pragma unroll
            for (int nb = 0; nb < 4; nb++) {
                int row = wn * 64 + nb * 16 + a_r;
                ldsm_x4(bq[nb], base + ATILE + row * ROWB + (kk * 16 + a_c8) * 2);
            }
            #pragma unroll
            for (int mi = 0; mi < 4; mi++)
                #pragma unroll
                for (int nb = 0; nb < 4; nb++) {
                    mma16816b(acc[mi][2*nb],   af[mi], bq[nb][0], bq[nb][2]);
                    mma16816b(acc[mi][2*nb+1], af[mi], bq[nb][1], bq[nb][3]);
                }
        }
    }

    int qr = lane >> 2, qc = (lane & 3) * 2;
    #pragma unroll
    for (int mi = 0; mi < 4; mi++) {
        #pragma unroll
        for (int ni = 0; ni < 8; ni++) {
            int gr = m0 + wm * 64 + mi * 16 + qr;
            int gc = n0 + wn * 64 + ni * 8 + qc;
            float b0 = bias[gc], b1 = bias[gc + 1];
            float v00 = acc[mi][ni][0] + b0, v01 = acc[mi][ni][1] + b1;
            float v10 = acc[mi][ni][2] + b0, v11 = acc[mi][ni][3] + b1;
            if (EPI == 0) {
                *(float2*)(Cf + (size_t)gr * N + gc)       = make_float2(v00, v01);
                *(float2*)(Cf + (size_t)(gr + 8) * N + gc) = make_float2(v10, v11);
            } else if (EPI == 1) {
                v00 = fmaxf(v00, 0.f); v01 = fmaxf(v01, 0.f);
                v10 = fmaxf(v10, 0.f); v11 = fmaxf(v11, 0.f);
                store_h2(Ch, (size_t)gr * N + gc,       v00, v01);
                store_h2(Ch, (size_t)(gr + 8) * N + gc, v10, v11);
            } else {
                int hh = gc / 192, inner = gc - hh * 192;
                int ty = inner >> 6, d = inner & 63;
                int bb = gr >> 10, si = gr & 1023;
                size_t dst = ((size_t)(bb * HH + hh) * SS + si) * HDIM + d;
                int bb2 = (gr + 8) >> 10, si2 = (gr + 8) & 1023;
                size_t dst2 = ((size_t)(bb2 * HH + hh) * SS + si2) * HDIM + d;
                if (ty == 0) {
                    store_h2(g_q, dst,  v00 * 0.125f, v01 * 0.125f);
                    store_h2(g_q, dst2, v10 * 0.125f, v11 * 0.125f);
                } else if (ty == 1) {
                    store_h2(g_k, dst,  v00, v01);
                    store_h2(g_k, dst2, v10, v11);
                } else {
                    store_h2(g_v, dst,  v00, v01);
                    store_h2(g_v, dst2, v10, v11);
                }
            }
        }
    }
}

// ================= flash attention (k-tile 64, occupancy 2) =================
#define FA_ROWF 144
#define FA_KT 64
#define FA_TILE (FA_KT*FA_ROWF)      // 9216
#define FA_STAGE (2*FA_TILE)         // K + V: 18432
#define FA_NSTG 3
#define FA_SMEM (FA_NSTG*FA_STAGE)   // 55296 -> 2 CTAs/SM

__global__ __launch_bounds__(256, 2) void flash_attn(const float* __restrict__ mask)
{
    extern __shared__ char sm[];
    uint32_t sb = smem_u32(sm);
    int tid = threadIdx.x, lane = tid & 31, w = tid >> 5;
    int qt = blockIdx.x, bh = blockIdx.y;
    int b = bh >> 4, h = bh & 15;
    size_t head = (size_t)bh * SS * HDIM;

    // ---- stage Q (128 rows x 128B) into first 2 stages' space, consume to regs ----
    #pragma unroll
    for (int j = 0; j < 4; j++) {
        int ch = tid + 256 * j;
        int row = (ch >> 3) & 127, c = ch & 7;
        cp16(sb + row * FA_ROWF + c * 16,
             g_q + head + (size_t)(qt * 128 + row) * HDIM + c * 8);
    }
    CP_COMMIT(); CP_WAIT0();
    __syncthreads();

    uint32_t qf[4][4];
    {
        int ar = lane & 15, ac = (lane >> 4) * 8;
        #pragma unroll
        for (int kb = 0; kb < 4; kb++)
            ldsm_x4(qf[kb], sb + (w * 16 + ar) * FA_ROWF + (kb * 16 + ac) * 2);
    }
    __syncthreads();

    // KV stage: 2 tiles x 64 rows x 8 chunks = 1024 chunks of 16B
    auto load_kv = [&](int s, int kt) {
        uint32_t base = sb + s * FA_STAGE;
        size_t goff = head + (size_t)(kt * FA_KT) * HDIM;
        #pragma unroll
        for (int j = 0; j < 4; j++) {
            int ch = tid + 256 * j;
            int tile = ch >> 9, row = (ch >> 3) & 63, c = ch & 7;
            const __half* sp = (tile == 0) ? g_k : g_v;
            cp16(base + tile * FA_TILE + row * FA_ROWF + c * 16,
                 sp + goff + (size_t)row * HDIM + c * 8);
        }
    };
    load_kv(0, 0); CP_COMMIT();
    load_kv(1, 1); CP_COMMIT();

    int g = lane >> 2, t = lane & 3;
    int krow = (lane & 7) + ((lane >> 4) & 1) * 8, kcol = ((lane >> 3) & 1) * 8;
    int vrow = (lane & 7) + ((lane >> 3) & 1) * 8, vcol = ((lane >> 4) & 1) * 8;
    int qrow0 = qt * 128 + w * 16 + g;
    const float* mrow0 = mask + ((size_t)(b * SS + qrow0)) * SS;

    float m0v = -1e30f, m1v = -1e30f, l0v = 0.f, l1v = 0.f;
    float o[8][4];
    #pragma unroll
    for (int nf = 0; nf < 8; nf++)
        #pragma unroll
        for (int e = 0; e < 4; e++) o[nf][e] = 0.f;

    const int T = SS / FA_KT;   // 16
    for (int kt = 0; kt < T; kt++) {
        if (kt < T - 1) { CP_WAIT1(); } else { CP_WAIT0(); }
        __syncthreads();
        if (kt + 2 < T) { load_kv((kt + 2) % FA_NSTG, kt + 2); CP_COMMIT(); }
        uint32_t base = sb + (kt % FA_NSTG) * FA_STAGE;

        // ---- S = Q K^T over 64 k-cols ----
        float s[8][4];
        #pragma unroll
        for (int np = 0; np < 4; np++) {
            #pragma unroll
            for (int e = 0; e < 4; e++) { s[2*np][e] = 0.f; s[2*np+1][e] = 0.f; }
            #pragma unroll
            for (int kb = 0; kb < 4; kb++) {
                uint32_t ka = base + (np * 16 + krow) * FA_ROWF + (kb * 16 + kcol) * 2;
                uint32_t k4[4];
                ldsm_x4(k4, ka);
                mma16816b(s[2*np],   qf[kb], k4[0], k4[1]);
                mma16816b(s[2*np+1], qf[kb], k4[2], k4[3]);
            }
        }

        // ---- mask + online softmax ----
        float mx0 = -1e30f, mx1 = -1e30f;
        #pragma unroll
        for (int ni = 0; ni < 8; ni++) {
            const float* mp = mrow0 + kt * FA_KT + ni * 8 + 2 * t;
            float2 mk0 = *(const float2*)mp;
            float2 mk1 = *(const float2*)(mp + 8 * SS);
            s[ni][0] += mk0.x; s[ni][1] += mk0.y;
            s[ni][2] += mk1.x; s[ni][3] += mk1.y;
            mx0 = fmaxf(mx0, fmaxf(s[ni][0], s[ni][1]));
            mx1 = fmaxf(mx1, fmaxf(s[ni][2], s[ni][3]));
        }
        mx0 = fmaxf(mx0, __shfl_xor_sync(0xffffffffu, mx0, 1));
        mx0 = fmaxf(mx0, __shfl_xor_sync(0xffffffffu, mx0, 2));
        mx1 = fmaxf(mx1, __shfl_xor_sync(0xffffffffu, mx1, 1));
        mx1 = fmaxf(mx1, __shfl_xor_sync(0xffffffffu, mx1, 2));
        float mn0 = fmaxf(m0v, mx0), mn1 = fmaxf(m1v, mx1);
        float a0 = __expf(m0v - mn0), a1 = __expf(m1v - mn1);
        m0v = mn0; m1v = mn1;
        l0v *= a0; l1v *= a1;
        #pragma unroll
        for (int nf = 0; nf < 8; nf++) {
            o[nf][0] *= a0; o[nf][1] *= a0; o[nf][2] *= a1; o[nf][3] *= a1;
        }
        #pragma unroll
        for (int ni = 0; ni < 8; ni++) {
            s[ni][0] = __expf(s[ni][0] - mn0); s[ni][1] = __expf(s[ni][1] - mn0);
            s[ni][2] = __expf(s[ni][2] - mn1); s[ni][3] = __expf(s[ni][3] - mn1);
            l0v += s[ni][0] + s[ni][1];
            l1v += s[ni][2] + s[ni][3];
        }

        // ---- O += P V ----
        #pragma unroll
        for (int ks = 0; ks < 4; ks++) {
            uint32_t pa[4];
            pa[0] = pack2h(s[2*ks][0],   s[2*ks][1]);
            pa[1] = pack2h(s[2*ks][2],   s[2*ks][3]);
            pa[2] = pack2h(s[2*ks+1][0], s[2*ks+1][1]);
            pa[3] = pack2h(s[2*ks+1][2], s[2*ks+1][3]);
            #pragma unroll
            for (int nv = 0; nv < 4; nv++) {
                uint32_t va = base + FA_TILE + (ks * 16 + vrow) * FA_ROWF
                              + (nv * 16 + vcol) * 2;
                uint32_t v4[4];
                ldsm_x4_t(v4, va);
                mma16816b(o[2*nv],   pa, v4[0], v4[1]);
                mma16816b(o[2*nv+1], pa, v4[2], v4[3]);
            }
        }
    }

    l0v += __shfl_xor_sync(0xffffffffu, l0v, 1);
    l0v += __shfl_xor_sync(0xffffffffu, l0v, 2);
    l1v += __shfl_xor_sync(0xffffffffu, l1v, 1);
    l1v += __shfl_xor_sync(0xffffffffu, l1v, 2);
    float inv0 = 1.f / l0v, inv1 = 1.f / l1v;
    size_t orow0 = (size_t)(b * SS + qrow0) * DD + h * HDIM;
    size_t orow1 = orow0 + (size_t)8 * DD;
    #pragma unroll
    for (int nf = 0; nf < 8; nf++) {
        int col = nf * 8 + 2 * t;
        store_h2(g_vo, orow0 + col, o[nf][0] * inv0, o[nf][1] * inv0);
        store_h2(g_vo, orow1 + col, o[nf][2] * inv1, o[nf][3] * inv1);
    }
}

// ================= weight transpose (fp16 single) =================
__global__ __launch_bounds__(256) void wsplit_t(const float* __restrict__ W,
                                                __half* __restrict__ hi,
                                                int Kdim, int Ndim) {
    __shared__ float t[32][33];
    size_t loff = (size_t)blockIdx.z * Kdim * Ndim;
    const float* Wl = W + loff;
    __half* hil = hi + loff;
    int k0 = blockIdx.y * 32, n0 = blockIdx.x * 32;
    int tx = threadIdx.x, ty = threadIdx.y;
    #pragma unroll
    for (int i = 0; i < 32; i += 8)
        t[ty + i][tx] = Wl[(size_t)(k0 + ty + i) * Ndim + n0 + tx];
    __syncthreads();
    #pragma unroll
    for (int i = 0; i < 32; i += 8) {
        int n = n0 + ty + i, k = k0 + tx;
        hil[(size_t)n * Kdim + k] = __float2half_rn(t[tx][ty + i]);
    }
}

// ================= embed + PE =================
__global__ __launch_bounds__(256) void embed_kernel(const int* __restrict__ tokens,
                                                    const float* __restrict__ emb,
                                                    float* __restrict__ x,
                                                    __half* __restrict__ xh) {
    int row = blockIdx.x;
    int s = row & (SS - 1);
    int tok = tokens[row];
    const float* e = emb + (size_t)tok * DD;
    int d0 = threadIdx.x * 4;
    float v[4];
    #pragma unroll
    for (int j = 0; j < 4; j++) {
        int d = d0 + j;
        int i2 = d & ~1;
        float denom = powf(10000.0f, (float)i2 / (float)DD);
        float ang = (float)s / denom;
        float pe = (d & 1) ? cosf(ang) : sinf(ang);
        v[j] = e[d] + pe;
    }
    size_t base = (size_t)row * DD + d0;
    *(float4*)(x + base) = make_float4(v[0], v[1], v[2], v[3]);
    store_h2(xh, base, v[0], v[1]);
    store_h2(xh, base + 2, v[2], v[3]);
}

// ================= residual + LayerNorm =================
__device__ __forceinline__ float warpReduceSum(float v) {
    #pragma unroll
    for (int o = 16; o; o >>= 1) v += __shfl_xor_sync(0xffffffffu, v, o);
    return v;
}
__device__ __forceinline__ float blockReduceSum(float v, float* sh) {
    v = warpReduceSum(v);
    int w = threadIdx.x >> 5;
    __syncthreads();
    if ((threadIdx.x & 31) == 0) sh[w] = v;
    __syncthreads();
    if (threadIdx.x < 32) {
        float t = (threadIdx.x < 8) ? sh[threadIdx.x] : 0.f;
        t = warpReduceSum(t);
        if (threadIdx.x == 0) sh[0] = t;
    }
    __syncthreads();
    return sh[0];
}

__global__ __launch_bounds__(256) void ln_kernel(const float* __restrict__ x,
                                                 const float* __restrict__ y,
                                                 const float* __restrict__ gamma,
                                                 const float* __restrict__ beta,
                                                 float* __restrict__ out,
                                                 __half* __restrict__ oh) {
    __shared__ float sh[8];
    size_t row = blockIdx.x;
    int d0 = threadIdx.x * 4;
    float4 a = *(const float4*)(x + row * DD + d0);
    float4 b4 = *(const float4*)(y + row * DD + d0);
    float z[4] = { a.x + b4.x, a.y + b4.y, a.z + b4.z, a.w + b4.w };
    float ssum = z[0] + z[1] + z[2] + z[3];
    ssum = blockReduceSum(ssum, sh);
    float mean = ssum * (1.0f / DD);
    float d2 = 0.f;
    #pragma unroll
    for (int e = 0; e < 4; e++) { float u = z[e] - mean; d2 += u * u; }
    d2 = blockReduceSum(d2, sh);
    float inv = rsqrtf(d2 * (1.0f / DD) + EPSV);
    float4 g4 = *(const float4*)(gamma + d0);
    float4 be4 = *(const float4*)(beta + d0);
    float o0 = g4.x * ((z[0] - mean) * inv) + be4.x;
    float o1 = g4.y * ((z[1] - mean) * inv) + be4.y;
    float o2 = g4.z * ((z[2] - mean) * inv) + be4.z;
    float o3 = g4.w * ((z[3] - mean) * inv) + be4.w;
    size_t base = row * DD + d0;
    *(float4*)(out + base) = make_float4(o0, o1, o2, o3);
    store_h2(oh, base, o0, o1);
    store_h2(oh, base + 2, o2, o3);
}

// ================= orchestration =================
extern "C" void kernel_launch(void* const* d_in, const int* in_sizes, int n_in,
                              void* d_out, int out_size) {
    const int*   tokens = (const int*)d_in[0];
    const float* mask   = (const float*)d_in[1];
    const float* emb    = (const float*)d_in[2];
    const float* qkv_w  = (const float*)d_in[3];
    const float* qkv_b  = (const float*)d_in[4];
    const float* out_w  = (const float*)d_in[5];
    const float* out_b  = (const float*)d_in[6];
    const float* w1     = (const float*)d_in[7];
    const float* b1     = (const float*)d_in[8];
    const float* w2     = (const float*)d_in[9];
    const float* b2     = (const float*)d_in[10];
    const float* gamma  = (const float*)d_in[11];
    const float* beta   = (const float*)d_in[12];
    float* out = (float*)d_out;

    float *px, *py;
    cudaGetSymbolAddress((void**)&px, g_x);
    cudaGetSymbolAddress((void**)&py, g_y);
    __half *pa, *pffa, *pvo, *pwq, *pwo, *pw1, *pw2;
    cudaGetSymbolAddress((void**)&pa,   g_a);
    cudaGetSymbolAddress((void**)&pffa, g_ffa);
    cudaGetSymbolAddress((void**)&pvo,  g_vo);
    cudaGetSymbolAddress((void**)&pwq,  g_wqkv);
    cudaGetSymbolAddress((void**)&pwo,  g_wout);
    cudaGetSymbolAddress((void**)&pw1,  g_w1);
    cudaGetSymbolAddress((void**)&pw2,  g_w2);

    cudaFuncSetAttribute(gemm_mma<0>, cudaFuncAttributeMaxDynamicSharedMemorySize, GT_SMEM);
    cudaFuncSetAttribute(gemm_mma<1>, cudaFuncAttributeMaxDynamicSharedMemorySize, GT_SMEM);
    cudaFuncSetAttribute(gemm_mma<2>, cudaFuncAttributeMaxDynamicSharedMemorySize, GT_SMEM);
    cudaFuncSetAttribute(flash_attn, cudaFuncAttributeMaxDynamicSharedMemorySize, FA_SMEM);

    wsplit_t<<<dim3(3 * DD / 32, DD / 32, LL), dim3(32, 8)>>>(qkv_w, pwq, DD, 3 * DD);
    wsplit_t<<<dim3(DD / 32, DD / 32, LL),     dim3(32, 8)>>>(out_w, pwo, DD, DD);
    wsplit_t<<<dim3(FF / 32, DD / 32, LL),     dim3(32, 8)>>>(w1, pw1, DD, FF);
    wsplit_t<<<dim3(DD / 32, FF / 32, LL),     dim3(32, 8)>>>(w2, pw2, FF, DD);

    embed_kernel<<<MM, 256>>>(tokens, emb, px, pa);

    for (int i = 0; i < LL; i++) {
        size_t l = (size_t)i;
        gemm_mma<2><<<dim3(3 * DD / GBN, MM / GBM), 256, GT_SMEM>>>(
            pa, pwq + l * 3 * DD * DD, qkv_b + l * 3 * DD, nullptr, nullptr, 3 * DD, DD);
        flash_attn<<<dim3(SS / 128, BB * HH), 256, FA_SMEM>>>(mask);
        gemm_mma<0><<<dim3(DD / GBN, MM / GBM), 256, GT_SMEM>>>(
            pvo, pwo + l * DD * DD, out_b + l * DD, py, nullptr, DD, DD);
        ln_kernel<<<MM, 256>>>(px, py, gamma + l * DD, beta + l * DD, px, pa);
        gemm_mma<1><<<dim3(FF / GBN, MM / GBM), 256, GT_SMEM>>>(
            pa, pw1 + l * DD * FF, b1 + l * FF, nullptr, pffa, FF, DD);
        gemm_mma<0><<<dim3(DD / GBN, MM / GBM), 256, GT_SMEM>>>(
            pffa, pw2 + l * FF * DD, b2 + l * DD, py, nullptr, DD, FF);
        ln_kernel<<<MM, 256>>>(px, py, gamma + l * DD, beta + l * DD,
                               (i == LL - 1) ? out : px, pa);
    }
}

// round 11
// speedup vs baseline: 1.4099x; 1.0140x over previous
#include <cuda_runtime.h>
#include <cuda_fp16.h>
#include <math.h>
#include <stdint.h>

#define BB 4
#define SS 1024
#define DD 1024
#define HH 16
#define HDIM 64
#define FF 4096
#define LL 6
#define MM (BB*SS)
#define EPSV 1e-5f

// ---------------- scratch (device globals; no allocation allowed) ----------------
__device__ float g_x[MM*DD];
__device__ __half g_y[MM*DD];
__device__ __half g_a[MM*DD];
__device__ __half g_ffa[MM*FF];
__device__ __half g_q[BB*HH*SS*HDIM];
__device__ __half g_k[BB*HH*SS*HDIM];
__device__ __half g_v[BB*HH*SS*HDIM];
__device__ __half g_vo[MM*DD];
__device__ __half g_mask[(size_t)BB*SS*SS];
__device__ __half g_wqkv[(size_t)LL*3*DD*DD];
__device__ __half g_wout[(size_t)LL*DD*DD];
__device__ __half g_w1[(size_t)LL*DD*FF];
__device__ __half g_w2[(size_t)LL*FF*DD];

// ================= PTX building blocks =================
__device__ __forceinline__ uint32_t smem_u32(const void* p) {
    return (uint32_t)__cvta_generic_to_shared((void*)p);
}
__device__ __forceinline__ void ldsm_x4(uint32_t (&r)[4], uint32_t addr) {
    asm volatile("ldmatrix.sync.aligned.m8n8.x4.shared.b16 {%0,%1,%2,%3}, [%4];"
        : "=r"(r[0]), "=r"(r[1]), "=r"(r[2]), "=r"(r[3]) : "r"(addr));
}
__device__ __forceinline__ void ldsm_x4_t(uint32_t (&r)[4], uint32_t addr) {
    asm volatile("ldmatrix.sync.aligned.m8n8.x4.trans.shared.b16 {%0,%1,%2,%3}, [%4];"
        : "=r"(r[0]), "=r"(r[1]), "=r"(r[2]), "=r"(r[3]) : "r"(addr));
}
__device__ __forceinline__ void mma16816b(float (&d)[4], const uint32_t (&a)[4],
                                          uint32_t b0, uint32_t b1) {
    asm volatile(
        "mma.sync.aligned.m16n8k16.row.col.f32.f16.f16.f32 "
        "{%0,%1,%2,%3}, {%4,%5,%6,%7}, {%8,%9}, {%0,%1,%2,%3};"
        : "+f"(d[0]), "+f"(d[1]), "+f"(d[2]), "+f"(d[3])
        : "r"(a[0]), "r"(a[1]), "r"(a[2]), "r"(a[3]), "r"(b0), "r"(b1));
}
__device__ __forceinline__ void cp16(uint32_t dst, const void* src) {
    asm volatile("cp.async.cg.shared.global [%0], [%1], 16;" :: "r"(dst), "l"(src));
}
#define CP_COMMIT() asm volatile("cp.async.commit_group;" ::: "memory")
#define CP_WAIT2()  asm volatile("cp.async.wait_group 2;" ::: "memory")
#define CP_WAIT1()  asm volatile("cp.async.wait_group 1;" ::: "memory")
#define CP_WAIT0()  asm volatile("cp.async.wait_group 0;" ::: "memory")

__device__ __forceinline__ void store_h2(__half* p, size_t idx, float a, float b) {
    *(__half2*)(p + idx) = __floats2half2_rn(a, b);
}
__device__ __forceinline__ uint32_t pack2h(float a, float b) {
    __half2 h = __floats2half2_rn(a, b);
    return *(uint32_t*)&h;
}

// ================= tensor-core GEMM (fp16, 256x128 CTA tile, 4-stage) ============
// EPI: 0 = fp16 C; 1 = ReLU + fp16 C; 2 = QKV scatter.
#define GBM 256
#define GBN 128
#define GBK 32
#define ROWB 80
#define ATILE (256*ROWB)
#define BTILE (128*ROWB)
#define STAGEB (ATILE+BTILE)
#define NSTG 4
#define GT_SMEM (NSTG*STAGEB)

template<int EPI>
__global__ __launch_bounds__(256, 1) void gemm_mma(
    const __half* __restrict__ A, const __half* __restrict__ B,
    const float* __restrict__ bias, __half* __restrict__ Ch, int N, int K)
{
    extern __shared__ char sm[];
    uint32_t sb = smem_u32(sm);
    int tid = threadIdx.x;
    int warp = tid >> 5, lane = tid & 31;
    int wm = warp >> 1, wn = warp & 1;
    int m0 = blockIdx.y * GBM, n0 = blockIdx.x * GBN;

    float acc[4][8][4];
    #pragma unroll
    for (int i = 0; i < 4; i++)
        #pragma unroll
        for (int j = 0; j < 8; j++)
            #pragma unroll
            for (int e = 0; e < 4; e++) acc[i][j][e] = 0.f;

    auto load_stage = [&](int s, int k0) {
        uint32_t base = sb + s * STAGEB;
        #pragma unroll
        for (int j = 0; j < 6; j++) {
            int ch = tid + 256 * j;
            if (ch < 1024) {
                int r = ch >> 2, c = ch & 3;
                cp16(base + r * ROWB + c * 16, A + (size_t)(m0 + r) * K + k0 + c * 8);
            } else {
                int idx = ch - 1024;
                int r = idx >> 2, c = idx & 3;
                cp16(base + ATILE + r * ROWB + c * 16,
                     B + (size_t)(n0 + r) * K + k0 + c * 8);
            }
        }
    };

    int T = K / GBK;
    load_stage(0, 0);          CP_COMMIT();
    load_stage(1, GBK);        CP_COMMIT();
    load_stage(2, 2 * GBK);    CP_COMMIT();

    int a_r = lane & 15, a_c8 = (lane >> 4) * 8;

    for (int t = 0; t < T; t++) {
        if (t + 2 < T)      { CP_WAIT2(); }
        else if (t + 1 < T) { CP_WAIT1(); }
        else                { CP_WAIT0(); }
        __syncthreads();
        if (t + 3 < T) { load_stage((t + 3) & (NSTG - 1), (t + 3) * GBK); CP_COMMIT(); }

        uint32_t base = sb + (t & (NSTG - 1)) * STAGEB;
        #pragma unroll
        for (int kk = 0; kk < 2; kk++) {
            uint32_t af[4][4], bq[4][4];
            #pragma unroll
            for (int mi = 0; mi < 4; mi++) {
                int row = wm * 64 + mi * 16 + a_r;
                ldsm_x4(af[mi], base + row * ROWB + (kk * 16 + a_c8) * 2);
            }
            #pragma unroll
            for (int nb = 0; nb < 4; nb++) {
                int row = wn * 64 + nb * 16 + a_r;
                ldsm_x4(bq[nb], base + ATILE + row * ROWB + (kk * 16 + a_c8) * 2);
            }
            #pragma unroll
            for (int mi = 0; mi < 4; mi++)
                #pragma unroll
                for (int nb = 0; nb < 4; nb++) {
                    mma16816b(acc[mi][2*nb],   af[mi], bq[nb][0], bq[nb][2]);
                    mma16816b(acc[mi][2*nb+1], af[mi], bq[nb][1], bq[nb][3]);
                }
        }
    }

    int qr = lane >> 2, qc = (lane & 3) * 2;
    #pragma unroll
    for (int mi = 0; mi < 4; mi++) {
        #pragma unroll
        for (int ni = 0; ni < 8; ni++) {
            int gr = m0 + wm * 64 + mi * 16 + qr;
            int gc = n0 + wn * 64 + ni * 8 + qc;
            float b0 = bias[gc], b1 = bias[gc + 1];
            float v00 = acc[mi][ni][0] + b0, v01 = acc[mi][ni][1] + b1;
            float v10 = acc[mi][ni][2] + b0, v11 = acc[mi][ni][3] + b1;
            if (EPI == 0) {
                store_h2(Ch, (size_t)gr * N + gc,       v00, v01);
                store_h2(Ch, (size_t)(gr + 8) * N + gc, v10, v11);
            } else if (EPI == 1) {
                v00 = fmaxf(v00, 0.f); v01 = fmaxf(v01, 0.f);
                v10 = fmaxf(v10, 0.f); v11 = fmaxf(v11, 0.f);
                store_h2(Ch, (size_t)gr * N + gc,       v00, v01);
                store_h2(Ch, (size_t)(gr + 8) * N + gc, v10, v11);
            } else {
                int hh = gc / 192, inner = gc - hh * 192;
                int ty = inner >> 6, d = inner & 63;
                int bb = gr >> 10, si = gr & 1023;
                size_t dst = ((size_t)(bb * HH + hh) * SS + si) * HDIM + d;
                int bb2 = (gr + 8) >> 10, si2 = (gr + 8) & 1023;
                size_t dst2 = ((size_t)(bb2 * HH + hh) * SS + si2) * HDIM + d;
                if (ty == 0) {
                    store_h2(g_q, dst,  v00 * 0.125f, v01 * 0.125f);
                    store_h2(g_q, dst2, v10 * 0.125f, v11 * 0.125f);
                } else if (ty == 1) {
                    store_h2(g_k, dst,  v00, v01);
                    store_h2(g_k, dst2, v10, v11);
                } else {
                    store_h2(g_v, dst,  v00, v01);
                    store_h2(g_v, dst2, v10, v11);
                }
            }
        }
    }
}

// ================= flash attention (k-tile 64, occupancy 2, fp16 mask) ===========
#define FA_ROWF 144
#define FA_KT 64
#define FA_TILE (FA_KT*FA_ROWF)
#define FA_STAGE (2*FA_TILE)
#define FA_NSTG 3
#define FA_SMEM (FA_NSTG*FA_STAGE)

__global__ __launch_bounds__(256, 2) void flash_attn()
{
    extern __shared__ char sm[];
    uint32_t sb = smem_u32(sm);
    int tid = threadIdx.x, lane = tid & 31, w = tid >> 5;
    int qt = blockIdx.x, bh = blockIdx.y;
    int b = bh >> 4, h = bh & 15;
    size_t head = (size_t)bh * SS * HDIM;

    #pragma unroll
    for (int j = 0; j < 4; j++) {
        int ch = tid + 256 * j;
        int row = (ch >> 3) & 127, c = ch & 7;
        cp16(sb + row * FA_ROWF + c * 16,
             g_q + head + (size_t)(qt * 128 + row) * HDIM + c * 8);
    }
    CP_COMMIT(); CP_WAIT0();
    __syncthreads();

    uint32_t qf[4][4];
    {
        int ar = lane & 15, ac = (lane >> 4) * 8;
        #pragma unroll
        for (int kb = 0; kb < 4; kb++)
            ldsm_x4(qf[kb], sb + (w * 16 + ar) * FA_ROWF + (kb * 16 + ac) * 2);
    }
    __syncthreads();

    auto load_kv = [&](int s, int kt) {
        uint32_t base = sb + s * FA_STAGE;
        size_t goff = head + (size_t)(kt * FA_KT) * HDIM;
        #pragma unroll
        for (int j = 0; j < 4; j++) {
            int ch = tid + 256 * j;
            int tile = ch >> 9, row = (ch >> 3) & 63, c = ch & 7;
            const __half* sp = (tile == 0) ? g_k : g_v;
            cp16(base + tile * FA_TILE + row * FA_ROWF + c * 16,
                 sp + goff + (size_t)row * HDIM + c * 8);
        }
    };
    load_kv(0, 0); CP_COMMIT();
    load_kv(1, 1); CP_COMMIT();

    int g = lane >> 2, t = lane & 3;
    int krow = (lane & 7) + ((lane >> 4) & 1) * 8, kcol = ((lane >> 3) & 1) * 8;
    int vrow = (lane & 7) + ((lane >> 3) & 1) * 8, vcol = ((lane >> 4) & 1) * 8;
    int qrow0 = qt * 128 + w * 16 + g;
    const __half* mrow0 = g_mask + ((size_t)(b * SS + qrow0)) * SS;

    float m0v = -1e30f, m1v = -1e30f, l0v = 0.f, l1v = 0.f;
    float o[8][4];
    #pragma unroll
    for (int nf = 0; nf < 8; nf++)
        #pragma unroll
        for (int e = 0; e < 4; e++) o[nf][e] = 0.f;

    const int T = SS / FA_KT;   // 16
    for (int kt = 0; kt < T; kt++) {
        if (kt < T - 1) { CP_WAIT1(); } else { CP_WAIT0(); }
        __syncthreads();
        if (kt + 2 < T) { load_kv((kt + 2) % FA_NSTG, kt + 2); CP_COMMIT(); }
        uint32_t base = sb + (kt % FA_NSTG) * FA_STAGE;

        float s[8][4];
        #pragma unroll
        for (int np = 0; np < 4; np++) {
            #pragma unroll
            for (int e = 0; e < 4; e++) { s[2*np][e] = 0.f; s[2*np+1][e] = 0.f; }
            #pragma unroll
            for (int kb = 0; kb < 4; kb++) {
                uint32_t ka = base + (np * 16 + krow) * FA_ROWF + (kb * 16 + kcol) * 2;
                uint32_t k4[4];
                ldsm_x4(k4, ka);
                mma16816b(s[2*np],   qf[kb], k4[0], k4[1]);
                mma16816b(s[2*np+1], qf[kb], k4[2], k4[3]);
            }
        }

        float mx0 = -1e30f, mx1 = -1e30f;
        #pragma unroll
        for (int ni = 0; ni < 8; ni++) {
            const __half* mp = mrow0 + kt * FA_KT + ni * 8 + 2 * t;
            float2 f0 = __half22float2(*(const __half2*)mp);
            float2 f1 = __half22float2(*(const __half2*)(mp + 8 * SS));
            s[ni][0] += f0.x; s[ni][1] += f0.y;
            s[ni][2] += f1.x; s[ni][3] += f1.y;
            mx0 = fmaxf(mx0, fmaxf(s[ni][0], s[ni][1]));
            mx1 = fmaxf(mx1, fmaxf(s[ni][2], s[ni][3]));
        }
        mx0 = fmaxf(mx0, __shfl_xor_sync(0xffffffffu, mx0, 1));
        mx0 = fmaxf(mx0, __shfl_xor_sync(0xffffffffu, mx0, 2));
        mx1 = fmaxf(mx1, __shfl_xor_sync(0xffffffffu, mx1, 1));
        mx1 = fmaxf(mx1, __shfl_xor_sync(0xffffffffu, mx1, 2));
        float mn0 = fmaxf(m0v, mx0), mn1 = fmaxf(m1v, mx1);
        float a0 = __expf(m0v - mn0), a1 = __expf(m1v - mn1);
        m0v = mn0; m1v = mn1;
        l0v *= a0; l1v *= a1;
        #pragma unroll
        for (int nf = 0; nf < 8; nf++) {
            o[nf][0] *= a0; o[nf][1] *= a0; o[nf][2] *= a1; o[nf][3] *= a1;
        }
        #pragma unroll
        for (int ni = 0; ni < 8; ni++) {
            s[ni][0] = __expf(s[ni][0] - mn0); s[ni][1] = __expf(s[ni][1] - mn0);
            s[ni][2] = __expf(s[ni][2] - mn1); s[ni][3] = __expf(s[ni][3] - mn1);
            l0v += s[ni][0] + s[ni][1];
            l1v += s[ni][2] + s[ni][3];
        }

        #pragma unroll
        for (int ks = 0; ks < 4; ks++) {
            uint32_t pa[4];
            pa[0] = pack2h(s[2*ks][0],   s[2*ks][1]);
            pa[1] = pack2h(s[2*ks][2],   s[2*ks][3]);
            pa[2] = pack2h(s[2*ks+1][0], s[2*ks+1][1]);
            pa[3] = pack2h(s[2*ks+1][2], s[2*ks+1][3]);
            #pragma unroll
            for (int nv = 0; nv < 4; nv++) {
                uint32_t va = base + FA_TILE + (ks * 16 + vrow) * FA_ROWF
                              + (nv * 16 + vcol) * 2;
                uint32_t v4[4];
                ldsm_x4_t(v4, va);
                mma16816b(o[2*nv],   pa, v4[0], v4[1]);
                mma16816b(o[2*nv+1], pa, v4[2], v4[3]);
            }
        }
    }

    l0v += __shfl_xor_sync(0xffffffffu, l0v, 1);
    l0v += __shfl_xor_sync(0xffffffffu, l0v, 2);
    l1v += __shfl_xor_sync(0xffffffffu, l1v, 1);
    l1v += __shfl_xor_sync(0xffffffffu, l1v, 2);
    float inv0 = 1.f / l0v, inv1 = 1.f / l1v;
    size_t orow0 = (size_t)(b * SS + qrow0) * DD + h * HDIM;
    size_t orow1 = orow0 + (size_t)8 * DD;
    #pragma unroll
    for (int nf = 0; nf < 8; nf++) {
        int col = nf * 8 + 2 * t;
        store_h2(g_vo, orow0 + col, o[nf][0] * inv0, o[nf][1] * inv0);
        store_h2(g_vo, orow1 + col, o[nf][2] * inv1, o[nf][3] * inv1);
    }
}

// ================= mask fp32 -> fp16 =================
__global__ __launch_bounds__(256) void mask_cvt(const float* __restrict__ m,
                                                __half* __restrict__ mh) {
    size_t i = ((size_t)blockIdx.x * 256 + threadIdx.x) * 4;
    float4 v = *(const float4*)(m + i);
    store_h2(mh, i,     v.x, v.y);
    store_h2(mh, i + 2, v.z, v.w);
}

// ================= weight transpose (fp16 single) =================
__global__ __launch_bounds__(256) void wsplit_t(const float* __restrict__ W,
                                                __half* __restrict__ hi,
                                                int Kdim, int Ndim) {
    __shared__ float t[32][33];
    size_t loff = (size_t)blockIdx.z * Kdim * Ndim;
    const float* Wl = W + loff;
    __half* hil = hi + loff;
    int k0 = blockIdx.y * 32, n0 = blockIdx.x * 32;
    int tx = threadIdx.x, ty = threadIdx.y;
    #pragma unroll
    for (int i = 0; i < 32; i += 8)
        t[ty + i][tx] = Wl[(size_t)(k0 + ty + i) * Ndim + n0 + tx];
    __syncthreads();
    #pragma unroll
    for (int i = 0; i < 32; i += 8) {
        int n = n0 + ty + i, k = k0 + tx;
        hil[(size_t)n * Kdim + k] = __float2half_rn(t[tx][ty + i]);
    }
}

// ================= embed + PE =================
__global__ __launch_bounds__(256) void embed_kernel(const int* __restrict__ tokens,
                                                    const float* __restrict__ emb,
                                                    float* __restrict__ x,
                                                    __half* __restrict__ xh) {
    int row = blockIdx.x;
    int s = row & (SS - 1);
    int tok = tokens[row];
    const float* e = emb + (size_t)tok * DD;
    int d0 = threadIdx.x * 4;
    float v[4];
    #pragma unroll
    for (int j = 0; j < 4; j++) {
        int d = d0 + j;
        int i2 = d & ~1;
        float denom = powf(10000.0f, (float)i2 / (float)DD);
        float ang = (float)s / denom;
        float pe = (d & 1) ? cosf(ang) : sinf(ang);
        v[j] = e[d] + pe;
    }
    size_t base = (size_t)row * DD + d0;
    *(float4*)(x + base) = make_float4(v[0], v[1], v[2], v[3]);
    store_h2(xh, base, v[0], v[1]);
    store_h2(xh, base + 2, v[2], v[3]);
}

// ================= residual + LayerNorm (warp per row) =================
__global__ __launch_bounds__(256) void ln_kernel(const float* __restrict__ x,
                                                 const __half* __restrict__ y,
                                                 const float* __restrict__ gamma,
                                                 const float* __restrict__ beta,
                                                 float* __restrict__ out,
                                                 __half* __restrict__ oh) {
    int warp = threadIdx.x >> 5, lane = threadIdx.x & 31;
    size_t row = (size_t)blockIdx.x * 8 + warp;
    const float* xr = x + row * DD;
    const __half* yr = y + row * DD;
    float z[32];
    float ssum = 0.f;
    #pragma unroll
    for (int j = 0; j < 8; j++) {
        int c = j * 128 + lane * 4;
        float4 xv = *(const float4*)(xr + c);
        float2 y0 = __half22float2(*(const __half2*)(yr + c));
        float2 y1 = __half22float2(*(const __half2*)(yr + c + 2));
        z[4*j + 0] = xv.x + y0.x; z[4*j + 1] = xv.y + y0.y;
        z[4*j + 2] = xv.z + y1.x; z[4*j + 3] = xv.w + y1.y;
        ssum += z[4*j] + z[4*j+1] + z[4*j+2] + z[4*j+3];
    }
    #pragma unroll
    for (int o2 = 16; o2; o2 >>= 1) ssum += __shfl_xor_sync(0xffffffffu, ssum, o2);
    float mean = ssum * (1.0f / DD);
    float d2 = 0.f;
    #pragma unroll
    for (int e = 0; e < 32; e++) { float u = z[e] - mean; d2 += u * u; }
    #pragma unroll
    for (int o2 = 16; o2; o2 >>= 1) d2 += __shfl_xor_sync(0xffffffffu, d2, o2);
    float inv = rsqrtf(d2 * (1.0f / DD) + EPSV);
    #pragma unroll
    for (int j = 0; j < 8; j++) {
        int c = j * 128 + lane * 4;
        float4 g4 = *(const float4*)(gamma + c);
        float4 be4 = *(const float4*)(beta + c);
        float o0 = g4.x * ((z[4*j+0] - mean) * inv) + be4.x;
        float o1 = g4.y * ((z[4*j+1] - mean) * inv) + be4.y;
        float o2v = g4.z * ((z[4*j+2] - mean) * inv) + be4.z;
        float o3 = g4.w * ((z[4*j+3] - mean) * inv) + be4.w;
        size_t base = row * DD + c;
        *(float4*)(out + base) = make_float4(o0, o1, o2v, o3);
        store_h2(oh, base, o0, o1);
        store_h2(oh, base + 2, o2v, o3);
    }
}

// ================= orchestration =================
extern "C" void kernel_launch(void* const* d_in, const int* in_sizes, int n_in,
                              void* d_out, int out_size) {
    const int*   tokens = (const int*)d_in[0];
    const float* mask   = (const float*)d_in[1];
    const float* emb    = (const float*)d_in[2];
    const float* qkv_w  = (const float*)d_in[3];
    const float* qkv_b  = (const float*)d_in[4];
    const float* out_w  = (const float*)d_in[5];
    const float* out_b  = (const float*)d_in[6];
    const float* w1     = (const float*)d_in[7];
    const float* b1     = (const float*)d_in[8];
    const float* w2     = (const float*)d_in[9];
    const float* b2     = (const float*)d_in[10];
    const float* gamma  = (const float*)d_in[11];
    const float* beta   = (const float*)d_in[12];
    float* out = (float*)d_out;

    float *px;
    cudaGetSymbolAddress((void**)&px, g_x);
    __half *py, *pa, *pffa, *pvo, *pmh, *pwq, *pwo, *pw1, *pw2;
    cudaGetSymbolAddress((void**)&py,   g_y);
    cudaGetSymbolAddress((void**)&pa,   g_a);
    cudaGetSymbolAddress((void**)&pffa, g_ffa);
    cudaGetSymbolAddress((void**)&pvo,  g_vo);
    cudaGetSymbolAddress((void**)&pmh,  g_mask);
    cudaGetSymbolAddress((void**)&pwq,  g_wqkv);
    cudaGetSymbolAddress((void**)&pwo,  g_wout);
    cudaGetSymbolAddress((void**)&pw1,  g_w1);
    cudaGetSymbolAddress((void**)&pw2,  g_w2);

    cudaFuncSetAttribute(gemm_mma<0>, cudaFuncAttributeMaxDynamicSharedMemorySize, GT_SMEM);
    cudaFuncSetAttribute(gemm_mma<1>, cudaFuncAttributeMaxDynamicSharedMemorySize, GT_SMEM);
    cudaFuncSetAttribute(gemm_mma<2>, cudaFuncAttributeMaxDynamicSharedMemorySize, GT_SMEM);
    cudaFuncSetAttribute(flash_attn, cudaFuncAttributeMaxDynamicSharedMemorySize, FA_SMEM);

    wsplit_t<<<dim3(3 * DD / 32, DD / 32, LL), dim3(32, 8)>>>(qkv_w, pwq, DD, 3 * DD);
    wsplit_t<<<dim3(DD / 32, DD / 32, LL),     dim3(32, 8)>>>(out_w, pwo, DD, DD);
    wsplit_t<<<dim3(FF / 32, DD / 32, LL),     dim3(32, 8)>>>(w1, pw1, DD, FF);
    wsplit_t<<<dim3(DD / 32, FF / 32, LL),     dim3(32, 8)>>>(w2, pw2, FF, DD);
    mask_cvt<<<(int)((size_t)BB * SS * SS / 1024), 256>>>(mask, pmh);

    embed_kernel<<<MM, 256>>>(tokens, emb, px, pa);

    for (int i = 0; i < LL; i++) {
        size_t l = (size_t)i;
        gemm_mma<2><<<dim3(3 * DD / GBN, MM / GBM), 256, GT_SMEM>>>(
            pa, pwq + l * 3 * DD * DD, qkv_b + l * 3 * DD, nullptr, 3 * DD, DD);
        flash_attn<<<dim3(SS / 128, BB * HH), 256, FA_SMEM>>>();
        gemm_mma<0><<<dim3(DD / GBN, MM / GBM), 256, GT_SMEM>>>(
            pvo, pwo + l * DD * DD, out_b + l * DD, py, DD, DD);
        ln_kernel<<<MM / 8, 256>>>(px, py, gamma + l * DD, beta + l * DD, px, pa);
        gemm_mma<1><<<dim3(FF / GBN, MM / GBM), 256, GT_SMEM>>>(
            pa, pw1 + l * DD * FF, b1 + l * FF, pffa, FF, DD);
        gemm_mma<0><<<dim3(DD / GBN, MM / GBM), 256, GT_SMEM>>>(
            pffa, pw2 + l * FF * DD, b2 + l * DD, py, DD, FF);
        ln_kernel<<<MM / 8, 256>>>(px, py, gamma + l * DD, beta + l * DD,
                                   (i == LL - 1) ? out : px, pa);
    }
}